// round 1
// baseline (speedup 1.0000x reference)
#include <cuda_runtime.h>
#include <cuda_bf16.h>
#include <cstdint>

// Problem dims
#define BATCH   8192
#define FEAT    1024
#define PAGES   16384
#define TOPK    32

// ---------------- scratch (static device allocations; no cudaMalloc) ----------
__device__ float g_scores[(size_t)BATCH * PAGES];          // 512 MB
__device__ float g_decT[(size_t)PAGES * FEAT];             // 64 MB  (dec_w transposed: [page][feat])
__device__ float g_vals[(size_t)BATCH * TOPK];
__device__ int   g_idx [(size_t)BATCH * TOPK];

// ---------------- transpose dec_w [FEAT][PAGES] -> g_decT [PAGES][FEAT] -------
__global__ void transpose_kernel(const float* __restrict__ dec_w)
{
    __shared__ float tile[32][33];
    const int p0 = blockIdx.x * 32;
    const int f0 = blockIdx.y * 32;
    const int tx = threadIdx.x;          // 32
    const int ty = threadIdx.y;          // 8
    #pragma unroll
    for (int j = 0; j < 32; j += 8)
        tile[ty + j][tx] = dec_w[(size_t)(f0 + ty + j) * PAGES + p0 + tx];
    __syncthreads();
    #pragma unroll
    for (int j = 0; j < 32; j += 8)
        g_decT[(size_t)(p0 + ty + j) * FEAT + f0 + tx] = tile[tx][ty + j];
}

// ---------------- fp32 SGEMM: scores = (x - bias) @ enc_w^T + enc_b -----------
// X [BATCH][FEAT] rm, W [PAGES][FEAT] rm. C[b][p] = sum_f (X[b][f]-bias[f])*W[p][f] + enc_b[p]
// Tile: BM=128, BN=128, BK=16, 256 threads, 8x8 per thread.
__global__ __launch_bounds__(256) void sgemm_kernel(
    const float* __restrict__ X,
    const float* __restrict__ W,
    const float* __restrict__ encb,
    const float* __restrict__ bias)
{
    constexpr int BK = 16;
    constexpr int LDS = 132;  // padded row stride (16B-aligned, reduces store conflicts)
    __shared__ float As[BK][LDS];
    __shared__ float Bs[BK][LDS];

    const int tid  = threadIdx.x;
    const int trow = tid >> 4;     // 0..15
    const int tcol = tid & 15;     // 0..15
    const int m0 = blockIdx.y * 128;
    const int n0 = blockIdx.x * 128;
    const int lrow = tid >> 2;            // 0..63
    const int lk   = (tid & 3) << 2;      // 0,4,8,12

    float acc[8][8];
    #pragma unroll
    for (int i = 0; i < 8; i++)
        #pragma unroll
        for (int j = 0; j < 8; j++) acc[i][j] = 0.f;

    const float* Xp0 = X + (size_t)(m0 + lrow) * FEAT + lk;
    const float* Xp1 = Xp0 + (size_t)64 * FEAT;
    const float* Wp0 = W + (size_t)(n0 + lrow) * FEAT + lk;
    const float* Wp1 = Wp0 + (size_t)64 * FEAT;

    for (int k0 = 0; k0 < FEAT; k0 += BK) {
        float4 a0 = *(const float4*)(Xp0 + k0);
        float4 a1 = *(const float4*)(Xp1 + k0);
        float4 b0 = *(const float4*)(Wp0 + k0);
        float4 b1 = *(const float4*)(Wp1 + k0);
        float4 bb = *(const float4*)(bias + k0 + lk);
        a0.x -= bb.x; a0.y -= bb.y; a0.z -= bb.z; a0.w -= bb.w;
        a1.x -= bb.x; a1.y -= bb.y; a1.z -= bb.z; a1.w -= bb.w;

        __syncthreads();
        As[lk + 0][lrow] = a0.x; As[lk + 1][lrow] = a0.y;
        As[lk + 2][lrow] = a0.z; As[lk + 3][lrow] = a0.w;
        As[lk + 0][lrow + 64] = a1.x; As[lk + 1][lrow + 64] = a1.y;
        As[lk + 2][lrow + 64] = a1.z; As[lk + 3][lrow + 64] = a1.w;
        Bs[lk + 0][lrow] = b0.x; Bs[lk + 1][lrow] = b0.y;
        Bs[lk + 2][lrow] = b0.z; Bs[lk + 3][lrow] = b0.w;
        Bs[lk + 0][lrow + 64] = b1.x; Bs[lk + 1][lrow + 64] = b1.y;
        Bs[lk + 2][lrow + 64] = b1.z; Bs[lk + 3][lrow + 64] = b1.w;
        __syncthreads();

        #pragma unroll
        for (int k = 0; k < BK; k++) {
            float4 ra0 = *(const float4*)&As[k][trow * 8];
            float4 ra1 = *(const float4*)&As[k][trow * 8 + 4];
            float4 rb0 = *(const float4*)&Bs[k][tcol * 8];
            float4 rb1 = *(const float4*)&Bs[k][tcol * 8 + 4];
            float ra[8] = {ra0.x, ra0.y, ra0.z, ra0.w, ra1.x, ra1.y, ra1.z, ra1.w};
            float rb[8] = {rb0.x, rb0.y, rb0.z, rb0.w, rb1.x, rb1.y, rb1.z, rb1.w};
            #pragma unroll
            for (int i = 0; i < 8; i++)
                #pragma unroll
                for (int j = 0; j < 8; j++)
                    acc[i][j] = fmaf(ra[i], rb[j], acc[i][j]);
        }
    }

    // epilogue: add enc_b, store fp32
    float4 eb0 = *(const float4*)(encb + n0 + tcol * 8);
    float4 eb1 = *(const float4*)(encb + n0 + tcol * 8 + 4);
    float eb[8] = {eb0.x, eb0.y, eb0.z, eb0.w, eb1.x, eb1.y, eb1.z, eb1.w};
    #pragma unroll
    for (int i = 0; i < 8; i++) {
        float* crow = g_scores + (size_t)(m0 + trow * 8 + i) * PAGES + n0 + tcol * 8;
        float4 o0 = {acc[i][0] + eb[0], acc[i][1] + eb[1], acc[i][2] + eb[2], acc[i][3] + eb[3]};
        float4 o1 = {acc[i][4] + eb[4], acc[i][5] + eb[5], acc[i][6] + eb[6], acc[i][7] + eb[7]};
        *(float4*)(crow)     = o0;
        *(float4*)(crow + 4) = o1;
    }
}

// ---------------- exact per-row top-32 via radix select ----------------------
// Key = float bits of positive value (monotone for positive floats); v<=0 -> key 0.
// Tie-break matches jax.lax.top_k: value desc, index asc. Zeros contribute nothing
// to the decode, so rows with <32 positives are padded with (0, 0).
#define CAND_CAP 1024

__global__ __launch_bounds__(256) void topk_kernel()
{
    const int row = blockIdx.x;
    const float* srow = g_scores + (size_t)row * PAGES;
    const int tid = threadIdx.x;

    __shared__ unsigned hist[256];
    __shared__ unsigned sprefix, scnt, sabove;
    __shared__ unsigned long long cand[CAND_CAP];
    __shared__ unsigned ccnt;
    __shared__ unsigned long long wbest[8];
    __shared__ int wpos[8];

    if (tid == 0) { sprefix = 0; sabove = 0; }
    __syncthreads();

    int shift = 24;
    for (int level = 0; level < 3; level++) {
        shift = 24 - 8 * level;
        hist[tid] = 0;
        __syncthreads();
        #pragma unroll 4
        for (int i = 0; i < PAGES / 256; i++) {
            const int c = tid + i * 256;
            const float v = srow[c];
            unsigned key = (v > 0.f) ? __float_as_uint(v) : 0u;
            bool ok = (level == 0) || ((key >> (shift + 8)) == sprefix);
            if (ok && key) atomicAdd(&hist[(key >> shift) & 255u], 1u);
        }
        __syncthreads();
        if (tid == 0) {
            unsigned c = sabove;
            int chosen = 0;
            unsigned cnt = c;
            for (int b = 255; b >= 0; b--) {
                unsigned nc = c + hist[b];
                if (nc >= TOPK) { chosen = b; cnt = nc; break; }
                c = nc;
                if (b == 0) { chosen = 0; cnt = nc; }
            }
            sabove = c;                       // strictly above chosen bin
            sprefix = (sprefix << 8) | (unsigned)chosen;
            scnt = cnt;                       // count >= (prefix << shift)
        }
        __syncthreads();
        if (scnt <= 64) break;
    }

    // collect candidates with key >= threshold
    const unsigned thresh = sprefix << shift;
    if (tid == 0) ccnt = 0;
    __syncthreads();
    for (int i = 0; i < PAGES / 256; i++) {
        const int c = tid + i * 256;
        const float v = srow[c];
        unsigned key = (v > 0.f) ? __float_as_uint(v) : 0u;
        if (key && key >= thresh) {
            unsigned pos = atomicAdd(&ccnt, 1u);
            if (pos < CAND_CAP)
                cand[pos] = ((unsigned long long)key << 32) |
                            (unsigned long long)(0xFFFFFFFFu - (unsigned)c);
        }
    }
    __syncthreads();
    const int n = (ccnt < CAND_CAP) ? (int)ccnt : CAND_CAP;
    const int lane = tid & 31, warp = tid >> 5;

    // 32 extraction rounds: max key, then min index (packed as ~idx in low bits)
    for (int r = 0; r < TOPK; r++) {
        unsigned long long best = 0; int bpos = -1;
        for (int j = tid; j < n; j += 256) {
            unsigned long long v = cand[j];
            if (v > best) { best = v; bpos = j; }
        }
        #pragma unroll
        for (int off = 16; off; off >>= 1) {
            unsigned long long ob = __shfl_down_sync(0xFFFFFFFFu, best, off);
            int op = __shfl_down_sync(0xFFFFFFFFu, bpos, off);
            if (ob > best) { best = ob; bpos = op; }
        }
        if (lane == 0) { wbest[warp] = best; wpos[warp] = bpos; }
        __syncthreads();
        if (tid == 0) {
            unsigned long long gb = 0; int gp = -1;
            #pragma unroll
            for (int w = 0; w < 8; w++)
                if (wbest[w] > gb) { gb = wbest[w]; gp = wpos[w]; }
            if (gb != 0ull) {
                g_vals[(size_t)row * TOPK + r] = __uint_as_float((unsigned)(gb >> 32));
                g_idx [(size_t)row * TOPK + r] = (int)(0xFFFFFFFFu - (unsigned)(gb & 0xFFFFFFFFu));
                cand[gp] = 0ull;
            } else {
                g_vals[(size_t)row * TOPK + r] = 0.f;
                g_idx [(size_t)row * TOPK + r] = 0;
            }
        }
        __syncthreads();
    }
}

// ---------------- decode: out[b][f] = bias[f] + sum_k vals*decT[idx][f] -------
__global__ __launch_bounds__(256) void decode_kernel(const float* __restrict__ bias,
                                                     float* __restrict__ out)
{
    const int row = blockIdx.x;
    const int tid = threadIdx.x;
    __shared__ float sv[TOPK];
    __shared__ int   si[TOPK];
    if (tid < TOPK) {
        sv[tid] = g_vals[(size_t)row * TOPK + tid];
        si[tid] = g_idx [(size_t)row * TOPK + tid];
    }
    __syncthreads();

    float acc[4];
    #pragma unroll
    for (int j = 0; j < 4; j++) acc[j] = bias[tid + j * 256];

    #pragma unroll 4
    for (int k = 0; k < TOPK; k++) {
        const float v = sv[k];
        if (v != 0.f) {
            const float* dr = g_decT + (size_t)si[k] * FEAT;
            #pragma unroll
            for (int j = 0; j < 4; j++)
                acc[j] = fmaf(v, dr[tid + j * 256], acc[j]);
        }
    }
    float* orow = out + (size_t)row * FEAT;
    #pragma unroll
    for (int j = 0; j < 4; j++) orow[tid + j * 256] = acc[j];
}

// ---------------- launch ------------------------------------------------------
extern "C" void kernel_launch(void* const* d_in, const int* in_sizes, int n_in,
                              void* d_out, int out_size)
{
    const float* x     = (const float*)d_in[0];   // [8192,1024]
    const float* enc_w = (const float*)d_in[1];   // [16384,1024]
    const float* enc_b = (const float*)d_in[2];   // [16384]
    const float* dec_w = (const float*)d_in[3];   // [1024,16384]
    const float* bias  = (const float*)d_in[4];   // [1024]
    float* out = (float*)d_out;                   // [8192,1024]

    transpose_kernel<<<dim3(PAGES / 32, FEAT / 32), dim3(32, 8)>>>(dec_w);
    sgemm_kernel<<<dim3(PAGES / 128, BATCH / 128), 256>>>(x, enc_w, enc_b, bias);
    topk_kernel<<<BATCH, 256>>>();
    decode_kernel<<<BATCH, 256>>>(bias, out);
}

// round 3
// speedup vs baseline: 4.4138x; 4.4138x over previous
#include <cuda_runtime.h>
#include <cuda_bf16.h>
#include <cstdint>

#define BATCH   8192
#define FEAT    1024
#define PAGES   16384
#define TOPK    32
#define CAP     96
#define TSEL    48

// ---------------- static device scratch ----------------
__device__ __nv_bfloat16 g_sc[(size_t)BATCH * PAGES];   // bf16 scores, 256 MB
__device__ __nv_bfloat16 g_A[(size_t)BATCH * FEAT];     // bf16(x - bias)
__device__ __nv_bfloat16 g_B[(size_t)PAGES * FEAT];     // bf16(enc_w)
__device__ float g_decT[(size_t)PAGES * FEAT];          // dec_w transposed
__device__ int   g_cand[(size_t)BATCH * CAP];
__device__ int   g_ccnt[BATCH];

__device__ __forceinline__ uint32_t smem_to_u32(const void* p) {
    uint32_t a;
    asm("{ .reg .u64 t; cvta.to.shared.u64 t, %1; cvt.u32.u64 %0, t; }" : "=r"(a) : "l"(p));
    return a;
}
#define CP_ASYNC16(dst, src) \
    asm volatile("cp.async.cg.shared.global [%0], [%1], 16;" :: "r"((uint32_t)(dst)), "l"(src) : "memory")
#define CP_COMMIT() asm volatile("cp.async.commit_group;" ::: "memory")
#define CP_WAIT1()  asm volatile("cp.async.wait_group 1;" ::: "memory")
#define CP_WAIT0()  asm volatile("cp.async.wait_group 0;" ::: "memory")

__device__ __forceinline__ void ldm_x4(uint32_t* f, uint32_t addr) {
    asm volatile("ldmatrix.sync.aligned.m8n8.x4.shared.b16 {%0,%1,%2,%3}, [%4];"
                 : "=r"(f[0]), "=r"(f[1]), "=r"(f[2]), "=r"(f[3]) : "r"(addr));
}
__device__ __forceinline__ void mma16816(float* c, const uint32_t* a, const uint32_t* b) {
    asm volatile("mma.sync.aligned.m16n8k16.row.col.f32.bf16.bf16.f32 "
                 "{%0,%1,%2,%3}, {%4,%5,%6,%7}, {%8,%9}, {%0,%1,%2,%3};"
                 : "+f"(c[0]), "+f"(c[1]), "+f"(c[2]), "+f"(c[3])
                 : "r"(a[0]), "r"(a[1]), "r"(a[2]), "r"(a[3]), "r"(b[0]), "r"(b[1]));
}

// ---------------- prep: bf16 conversions ----------------
__global__ __launch_bounds__(256) void prep_x_kernel(const float* __restrict__ x,
                                                     const float* __restrict__ bias) {
    int g = blockIdx.x * 256 + threadIdx.x;
    float4 v = ((const float4*)x)[g];
    float4 b = ((const float4*)bias)[g & 255];
    __nv_bfloat162 lo = __floats2bfloat162_rn(v.x - b.x, v.y - b.y);
    __nv_bfloat162 hi = __floats2bfloat162_rn(v.z - b.z, v.w - b.w);
    uint2 o; o.x = *(uint32_t*)&lo; o.y = *(uint32_t*)&hi;
    ((uint2*)g_A)[g] = o;
}
__global__ __launch_bounds__(256) void prep_w_kernel(const float* __restrict__ w) {
    int g = blockIdx.x * 256 + threadIdx.x;
    float4 v = ((const float4*)w)[g];
    __nv_bfloat162 lo = __floats2bfloat162_rn(v.x, v.y);
    __nv_bfloat162 hi = __floats2bfloat162_rn(v.z, v.w);
    uint2 o; o.x = *(uint32_t*)&lo; o.y = *(uint32_t*)&hi;
    ((uint2*)g_B)[g] = o;
}

// ---------------- transpose dec_w [F][P] -> g_decT [P][F] ----------------
__global__ void transpose_kernel(const float* __restrict__ dec_w) {
    __shared__ float tile[32][33];
    const int p0 = blockIdx.x * 32, f0 = blockIdx.y * 32;
    const int tx = threadIdx.x, ty = threadIdx.y;
    #pragma unroll
    for (int j = 0; j < 32; j += 8)
        tile[ty + j][tx] = dec_w[(size_t)(f0 + ty + j) * PAGES + p0 + tx];
    __syncthreads();
    #pragma unroll
    for (int j = 0; j < 32; j += 8)
        g_decT[(size_t)(p0 + ty + j) * FEAT + f0 + tx] = tile[tx][ty + j];
}

// ---------------- bf16 HMMA GEMM: scores = A @ B^T + enc_b -> bf16 ----------------
// Tile BM=128, BN=128, BK=32, 3-stage cp.async, 256 threads (8 warps 2Mx4N, warp=64x32).
#define BK 32
#define STAGES 3
#define STAGE_BYTES 16384      // A 8KB + B 8KB
#define KT (FEAT / BK)         // 32

__global__ __launch_bounds__(256, 2) void gemm_kernel(const float* __restrict__ encb) {
    __shared__ __align__(1024) char smem[STAGES * STAGE_BYTES];
    const uint32_t sb = smem_to_u32(smem);

    const int tid = threadIdx.x, wid = tid >> 5, lane = tid & 31;
    const int warp_m = wid >> 2, warp_n = wid & 3;      // 2 x 4
    const int m_off = warp_m * 64, n_off = warp_n * 32;
    const int m0 = blockIdx.y * 128, n0 = blockIdx.x * 128;

    // cp.async per-thread source/dest (2 chunks each for A and B per stage)
    const int ldr = tid >> 2;          // 0..63  (x2 -> 128 rows)
    const int ldc = tid & 3;           // c8
    const __nv_bfloat16* Abase = g_A + (size_t)m0 * FEAT;
    const __nv_bfloat16* Bbase = g_B + (size_t)n0 * FEAT;

    // ldmatrix lane geometry
    const int rowA = lane & 15, kcA = lane >> 4;
    const int rowB = ((lane >> 4) << 3) + (lane & 7), kcB = (lane >> 3) & 1;

    int amr[4], bnr[2];
    #pragma unroll
    for (int mt = 0; mt < 4; mt++) amr[mt] = m_off + mt * 16 + rowA;
    #pragma unroll
    for (int ng = 0; ng < 2; ng++) bnr[ng] = n_off + ng * 16 + rowB;

    float acc[4][4][4];
    #pragma unroll
    for (int i = 0; i < 4; i++)
        #pragma unroll
        for (int j = 0; j < 4; j++)
            #pragma unroll
            for (int q = 0; q < 4; q++) acc[i][j][q] = 0.f;

    auto load_stage = [&](int kt, int slot) {
        const uint32_t base = sb + slot * STAGE_BYTES;
        #pragma unroll
        for (int h = 0; h < 2; h++) {
            int r = ldr + h * 64;
            uint32_t sw = (uint32_t)(ldc ^ ((r >> 1) & 3)) << 4;
            CP_ASYNC16(base + r * 64 + sw, Abase + (size_t)r * FEAT + kt * BK + ldc * 8);
            CP_ASYNC16(base + 8192 + r * 64 + sw, Bbase + (size_t)r * FEAT + kt * BK + ldc * 8);
        }
    };

    load_stage(0, 0); CP_COMMIT();
    load_stage(1, 1); CP_COMMIT();

    for (int kt = 0; kt < KT; kt++) {
        if (kt == KT - 1) { CP_WAIT0(); } else { CP_WAIT1(); }
        __syncthreads();
        const int slot = kt % STAGES;
        if (kt + 2 < KT) { load_stage(kt + 2, (kt + 2) % STAGES); CP_COMMIT(); }

        const uint32_t abase = sb + slot * STAGE_BYTES;
        const uint32_t bbase = abase + 8192;
        #pragma unroll
        for (int ks = 0; ks < 2; ks++) {
            uint32_t af[4][4], bf[2][4];
            #pragma unroll
            for (int mt = 0; mt < 4; mt++) {
                int r = amr[mt];
                uint32_t sw = (uint32_t)(((ks * 2 + kcA) ^ ((r >> 1) & 3))) << 4;
                ldm_x4(af[mt], abase + r * 64 + sw);
            }
            #pragma unroll
            for (int ng = 0; ng < 2; ng++) {
                int r = bnr[ng];
                uint32_t sw = (uint32_t)(((ks * 2 + kcB) ^ ((r >> 1) & 3))) << 4;
                ldm_x4(bf[ng], bbase + r * 64 + sw);
            }
            #pragma unroll
            for (int mt = 0; mt < 4; mt++)
                #pragma unroll
                for (int nt = 0; nt < 4; nt++)
                    mma16816(acc[mt][nt], af[mt], &bf[nt >> 1][(nt & 1) * 2]);
        }
        __syncthreads();
    }

    // epilogue: add enc_b, pack bf16, store
    #pragma unroll
    for (int mt = 0; mt < 4; mt++) {
        const int r0 = m0 + m_off + mt * 16 + (lane >> 2);
        #pragma unroll
        for (int nt = 0; nt < 4; nt++) {
            const int n = n0 + n_off + nt * 8 + (lane & 3) * 2;
            const float e0 = encb[n], e1 = encb[n + 1];
            __nv_bfloat162 lo = __floats2bfloat162_rn(acc[mt][nt][0] + e0, acc[mt][nt][1] + e1);
            __nv_bfloat162 hi = __floats2bfloat162_rn(acc[mt][nt][2] + e0, acc[mt][nt][3] + e1);
            *(uint32_t*)(g_sc + (size_t)r0 * PAGES + n)       = *(uint32_t*)&lo;
            *(uint32_t*)(g_sc + (size_t)(r0 + 8) * PAGES + n) = *(uint32_t*)&hi;
        }
    }
}

// ---------------- candidate select: top-~48 per row by bf16 key ----------------
__global__ __launch_bounds__(256) void select_kernel() {
    const int row = blockIdx.x, tid = threadIdx.x;
    __shared__ unsigned short svl[PAGES];
    __shared__ unsigned hist[256];
    __shared__ unsigned s_thr, s_hb, s_above, scnt;

    hist[tid] = 0;
    if (tid == 0) scnt = 0;
    __syncthreads();

    const uint4* src = (const uint4*)(g_sc + (size_t)row * PAGES);
    uint4* dst = (uint4*)svl;
    #pragma unroll
    for (int i = 0; i < 8; i++) {
        int idx = tid + i * 256;
        uint4 v = src[idx];
        dst[idx] = v;
        unsigned w[4] = { v.x, v.y, v.z, v.w };
        #pragma unroll
        for (int q = 0; q < 4; q++) {
            unsigned a = w[q] & 0xFFFFu, b = w[q] >> 16;
            if (a && !(a & 0x8000u)) atomicAdd(&hist[a >> 8], 1u);
            if (b && !(b & 0x8000u)) atomicAdd(&hist[b >> 8], 1u);
        }
    }
    __syncthreads();
    if (tid == 0) {
        unsigned c = 0; int hb = -1; unsigned above = 0;
        for (int b = 255; b >= 1; b--) {
            unsigned nc = c + hist[b];
            if (nc >= TSEL) { hb = b; above = c; break; }
            c = nc;
        }
        if (hb < 0) { s_thr = 1; s_hb = 256; }
        else        { s_hb = (unsigned)hb; s_above = above; }
    }
    __syncthreads();
    if (s_hb < 256) {
        hist[tid] = 0;
        __syncthreads();
        const unsigned hb = s_hb;
        for (int i = 0; i < PAGES / 256; i++) {
            unsigned u = svl[tid + i * 256];
            if (u && !(u & 0x8000u) && (u >> 8) == hb) atomicAdd(&hist[u & 255u], 1u);
        }
        __syncthreads();
        if (tid == 0) {
            unsigned c = s_above; unsigned lb = 0;
            for (int b = 255; b >= 0; b--) { c += hist[b]; if (c >= TSEL) { lb = (unsigned)b; break; } }
            s_thr = (s_hb << 8) | lb;
        }
        __syncthreads();
    }
    const unsigned thr = s_thr;
    for (int i = 0; i < PAGES / 256; i++) {
        int idx = tid + i * 256;
        unsigned u = svl[idx];
        unsigned key = (u && !(u & 0x8000u)) ? u : 0u;
        if (key >= thr && key) {
            unsigned p = atomicAdd(&scnt, 1u);
            if (p < CAP) g_cand[(size_t)row * CAP + p] = idx;
        }
    }
    __syncthreads();
    if (tid == 0) g_ccnt[row] = (scnt < CAP) ? (int)scnt : CAP;
}

// ---------------- exact rescore + top-32 + decode (fused) ----------------
__global__ __launch_bounds__(256) void rescore_decode_kernel(
    const float* __restrict__ x, const float* __restrict__ enc_w,
    const float* __restrict__ enc_b, const float* __restrict__ bias,
    float* __restrict__ out)
{
    const int row = blockIdx.x, tid = threadIdx.x, lane = tid & 31, warp = tid >> 5;
    __shared__ float xb[FEAT];
    __shared__ unsigned long long skey[CAP];
    __shared__ float sv[TOPK];
    __shared__ int   six[TOPK];
    __shared__ unsigned long long wmax[8];
    __shared__ int wpos[8];

    const int n = g_ccnt[row];
    #pragma unroll
    for (int j = 0; j < 4; j++) {
        int f = tid + j * 256;
        xb[f] = x[(size_t)row * FEAT + f] - bias[f];
    }
    if (tid < CAP) skey[tid] = 0ull;
    __syncthreads();

    for (int c = warp; c < n; c += 8) {
        const int idx = g_cand[(size_t)row * CAP + c];
        const float* wr = enc_w + (size_t)idx * FEAT;
        float s = 0.f;
        #pragma unroll 8
        for (int j = lane; j < FEAT; j += 32) s = fmaf(xb[j], __ldg(wr + j), s);
        #pragma unroll
        for (int o = 16; o; o >>= 1) s += __shfl_xor_sync(0xFFFFFFFFu, s, o);
        if (lane == 0) {
            s += enc_b[idx];
            skey[c] = (s > 0.f)
                ? (((unsigned long long)__float_as_uint(s) << 32) |
                   (unsigned long long)(0xFFFFFFFFu - (unsigned)idx))
                : 0ull;
        }
    }
    __syncthreads();

    for (int r = 0; r < TOPK; r++) {
        unsigned long long k = (tid < n) ? skey[tid] : 0ull;
        int p = tid;
        #pragma unroll
        for (int o = 16; o; o >>= 1) {
            unsigned long long ok = __shfl_down_sync(0xFFFFFFFFu, k, o);
            int op = __shfl_down_sync(0xFFFFFFFFu, p, o);
            if (ok > k) { k = ok; p = op; }
        }
        if (lane == 0) { wmax[warp] = k; wpos[warp] = p; }
        __syncthreads();
        if (tid == 0) {
            unsigned long long gb = 0; int gp = -1;
            #pragma unroll
            for (int w = 0; w < 8; w++)
                if (wmax[w] > gb) { gb = wmax[w]; gp = wpos[w]; }
            if (gb) {
                sv[r] = __uint_as_float((unsigned)(gb >> 32));
                six[r] = (int)(0xFFFFFFFFu - (unsigned)gb);
                skey[gp] = 0ull;
            } else { sv[r] = 0.f; six[r] = 0; }
        }
        __syncthreads();
    }

    float acc[4];
    #pragma unroll
    for (int j = 0; j < 4; j++) acc[j] = bias[tid + j * 256];
    for (int k = 0; k < TOPK; k++) {
        const float v = sv[k];
        if (v != 0.f) {
            const float* dr = g_decT + (size_t)six[k] * FEAT;
            #pragma unroll
            for (int j = 0; j < 4; j++) acc[j] = fmaf(v, dr[tid + j * 256], acc[j]);
        }
    }
    float* orow = out + (size_t)row * FEAT;
    #pragma unroll
    for (int j = 0; j < 4; j++) orow[tid + j * 256] = acc[j];
}

// ---------------- launch ----------------
extern "C" void kernel_launch(void* const* d_in, const int* in_sizes, int n_in,
                              void* d_out, int out_size)
{
    const float* x     = (const float*)d_in[0];
    const float* enc_w = (const float*)d_in[1];
    const float* enc_b = (const float*)d_in[2];
    const float* dec_w = (const float*)d_in[3];
    const float* bias  = (const float*)d_in[4];
    float* out = (float*)d_out;

    prep_x_kernel<<<BATCH * FEAT / 1024, 256>>>(x, bias);
    prep_w_kernel<<<PAGES * FEAT / 1024, 256>>>(enc_w);
    transpose_kernel<<<dim3(PAGES / 32, FEAT / 32), dim3(32, 8)>>>(dec_w);
    gemm_kernel<<<dim3(PAGES / 128, BATCH / 128), 256>>>(enc_b);
    select_kernel<<<BATCH, 256>>>();
    rescore_decode_kernel<<<BATCH, 256>>>(x, enc_w, enc_b, bias, out);
}